// round 8
// baseline (speedup 1.0000x reference)
#include <cuda_runtime.h>
#include <cuda_bf16.h>
#include <cstdint>

#define B_    128
#define LQ_   512
#define LD_   512
#define DIM   128
#define TM    128            // q rows per CTA
#define TN    64             // doc rows per chunk
#define NCHUNK (LD_ / TN)    // 8
#define NTHREADS 256

// ---- global scratch: pre-converted bf16 D + exact fp32 row norms ----
__device__ __nv_bfloat16 g_Dbf[B_ * LD_ * DIM];   // 16 MB
__device__ float         g_Dsq[B_ * LD_];         // 256 KB

// ---- kernel-2 smem layout (bytes) ----
#define SM_QS    0                      // 128x128 bf16 swizzled = 32768
#define SM_DS0   32768                  // bf16 chunk buf 0 (16384)
#define SM_DS1   49152                  // bf16 chunk buf 1 (16384)
#define SM_DSQ   65536                  // 512 floats = 2048
#define SM_QSQ   67584                  // 128 floats = 512
#define SM_MAX   68096                  // 128*2 floats = 1024
#define SM_RED   69120                  // 8 floats
#define SMEM_TOTAL (SM_RED + 64)        // 69184

__device__ __forceinline__ uint32_t smem_u32(const void* p) {
    uint32_t a;
    asm("{ .reg .u64 t; cvta.to.shared.u64 t, %1; cvt.u32.u64 %0, t; }" : "=r"(a) : "l"(p));
    return a;
}

__device__ __forceinline__ void ldmatrix_x4(uint32_t& r0, uint32_t& r1,
                                            uint32_t& r2, uint32_t& r3, uint32_t addr) {
    asm volatile("ldmatrix.sync.aligned.m8n8.x4.shared.b16 {%0,%1,%2,%3}, [%4];"
                 : "=r"(r0), "=r"(r1), "=r"(r2), "=r"(r3) : "r"(addr));
}

__device__ __forceinline__ void mma_16816(float& c0, float& c1, float& c2, float& c3,
                                          uint32_t a0, uint32_t a1, uint32_t a2, uint32_t a3,
                                          uint32_t b0, uint32_t b1) {
    asm volatile("mma.sync.aligned.m16n8k16.row.col.f32.bf16.bf16.f32 "
                 "{%0,%1,%2,%3}, {%4,%5,%6,%7}, {%8,%9}, {%0,%1,%2,%3};"
                 : "+f"(c0), "+f"(c1), "+f"(c2), "+f"(c3)
                 : "r"(a0), "r"(a1), "r"(a2), "r"(a3), "r"(b0), "r"(b1));
}

__device__ __forceinline__ void cp_async16(uint32_t dst, const void* src) {
    asm volatile("cp.async.cg.shared.global [%0], [%1], 16;" :: "r"(dst), "l"(src));
}
__device__ __forceinline__ void cp_commit() {
    asm volatile("cp.async.commit_group;" ::: "memory");
}
template <int N>
__device__ __forceinline__ void cp_wait() {
    asm volatile("cp.async.wait_group %0;" :: "n"(N) : "memory");
}

// ================= kernel 1: D fp32 -> bf16 + exact row norms (+ zero out) ====
__global__ void __launch_bounds__(NTHREADS)
convert_d_kernel(const float* __restrict__ Dg, float* __restrict__ out) {
    const int tid = threadIdx.x;
    const int w = tid >> 5, l = tid & 31;
    const int rsub = l >> 3;
    const int piece = l & 7;

    if (blockIdx.x == 0 && tid < B_) out[tid] = 0.0f;

    #pragma unroll
    for (int pass = 0; pass < 4; pass++) {
        int row = blockIdx.x * 128 + w * 16 + pass * 4 + rsub;
        const float4* src = reinterpret_cast<const float4*>(Dg + (size_t)row * DIM);
        float4 v[4];
        #pragma unroll
        for (int i = 0; i < 4; i++) v[i] = src[piece + 8 * i];

        float s = 0.0f;
        #pragma unroll
        for (int i = 0; i < 4; i++)
            s += v[i].x * v[i].x + v[i].y * v[i].y + v[i].z * v[i].z + v[i].w * v[i].w;
        s += __shfl_xor_sync(0xffffffffu, s, 1);
        s += __shfl_xor_sync(0xffffffffu, s, 2);
        s += __shfl_xor_sync(0xffffffffu, s, 4);
        if (piece == 0) g_Dsq[row] = s;

        uint2* drow = reinterpret_cast<uint2*>(g_Dbf + (size_t)row * DIM);
        #pragma unroll
        for (int i = 0; i < 4; i++) {
            __nv_bfloat162 p0 = __floats2bfloat162_rn(v[i].x, v[i].y);
            __nv_bfloat162 p1 = __floats2bfloat162_rn(v[i].z, v[i].w);
            drow[piece + 8 * i] = make_uint2(*reinterpret_cast<uint32_t*>(&p0),
                                             *reinterpret_cast<uint32_t*>(&p1));
        }
    }
}

// ================= kernel 2: GEMM + fused max/sum epilogue =================
__global__ void __launch_bounds__(NTHREADS, 3)
colbert_mma_kernel(const float* __restrict__ Qg, float* __restrict__ out) {
    extern __shared__ char smem[];
    const uint32_t sb = smem_u32(smem);
    float* dsq_s  = reinterpret_cast<float*>(smem + SM_DSQ);
    float* qsq    = reinterpret_cast<float*>(smem + SM_QSQ);
    float* maxbuf = reinterpret_cast<float*>(smem + SM_MAX);
    float* red    = reinterpret_cast<float*>(smem + SM_RED);

    const int tid = threadIdx.x;
    const int w = tid >> 5, l = tid & 31;
    const int wm = w >> 1;               // 0..3 : 32-row M block
    const int wn = w & 1;                // 0..1 : 32-col N block

    const int b  = blockIdx.x >> 2;
    const int qt = blockIdx.x & 3;
    const float* Qb = Qg + ((size_t)(b * LQ_ + qt * TM)) * DIM;
    const __nv_bfloat16* Dbf_b = g_Dbf + (size_t)b * LD_ * DIM;

    // ---- issue cp.async for chunks 0 and 1 (bf16, swizzled dst) ----
    // 1024 16B-granules per chunk; 4 per thread.
    {
        #pragma unroll
        for (int cbuf = 0; cbuf < 2; cbuf++) {
            const char* src_base = reinterpret_cast<const char*>(Dbf_b + (size_t)cbuf * TN * DIM);
            uint32_t dst_base = sb + SM_DS0 + (uint32_t)(cbuf * 16384);
            #pragma unroll
            for (int j = 0; j < 4; j++) {
                int idx = tid + 256 * j;
                int r = idx >> 4, cc = idx & 15;
                cp_async16(dst_base + (uint32_t)(r * 256 + (((cc ^ (r & 7)) << 4))),
                           src_base + r * 256 + cc * 16);
            }
            cp_commit();
        }
    }

    // ---- convert Q tile fp32 -> bf16(2*q) swizzled smem + qsq (overlapped) ----
    {
        char* qs = smem + SM_QS;
        #pragma unroll
        for (int j = 0; j < TM / 8; j++) {
            int row = j * 8 + w;
            float4 v = reinterpret_cast<const float4*>(Qb)[row * 32 + l];
            float s = v.x * v.x + v.y * v.y + v.z * v.z + v.w * v.w;
            #pragma unroll
            for (int o = 16; o > 0; o >>= 1) s += __shfl_xor_sync(0xffffffffu, s, o);
            if (l == 0) qsq[row] = s;
            __nv_bfloat162 p0 = __floats2bfloat162_rn(2.0f * v.x, 2.0f * v.y);
            __nv_bfloat162 p1 = __floats2bfloat162_rn(2.0f * v.z, 2.0f * v.w);
            uint2 pk = make_uint2(*reinterpret_cast<uint32_t*>(&p0),
                                  *reinterpret_cast<uint32_t*>(&p1));
            uint32_t addr = (uint32_t)(row * 256 + (((l >> 1) ^ (row & 7)) << 4) + ((l & 1) << 3));
            *reinterpret_cast<uint2*>(qs + addr) = pk;
        }
    }
    // ---- whole-batch doc norms into smem (512 floats) ----
    {
        const float* src = g_Dsq + b * LD_;
        dsq_s[tid] = src[tid];
        dsq_s[tid + 256] = src[tid + 256];
    }

    // ---- ldmatrix lane addressing (validated structure) ----
    const int jj = l >> 3;
    const int rr = l & 7;
    const int arow = wm * 32 + ((jj & 1) << 3) + rr;
    const int achunk_off = jj >> 1;
    const int asw = arow & 7;
    const int brow = wn * 32 + ((jj >> 1) << 3) + rr;
    const int bchunk_off = jj & 1;
    const int bsw = brow & 7;

    const int tg = l >> 2;
    const int tc = l & 3;

    float rlo[2], rhi[2];
    #pragma unroll
    for (int mt = 0; mt < 2; mt++) { rlo[mt] = -3.402823e38f; rhi[mt] = -3.402823e38f; }

    #pragma unroll
    for (int c = 0; c < NCHUNK; c++) {
        if (c < NCHUNK - 1) cp_wait<1>(); else cp_wait<0>();
        __syncthreads();   // chunk c visible to all

        const uint32_t ds_cur_u = sb + SM_DS0 + (uint32_t)((c & 1) * 16384);

        float acc[2][4][4];
        #pragma unroll
        for (int mt = 0; mt < 2; mt++)
            #pragma unroll
            for (int nt = 0; nt < 4; nt++)
                #pragma unroll
                for (int e = 0; e < 4; e++) acc[mt][nt][e] = 0.0f;

        #pragma unroll
        for (int k = 0; k < 8; k++) {
            uint32_t a[2][4];
            #pragma unroll
            for (int mt = 0; mt < 2; mt++) {
                uint32_t addr = sb + SM_QS + (uint32_t)((arow + mt * 16) * 256
                              + (((k * 2 + achunk_off) ^ asw) << 4));
                ldmatrix_x4(a[mt][0], a[mt][1], a[mt][2], a[mt][3], addr);
            }
            uint32_t bf[4][2];
            #pragma unroll
            for (int p = 0; p < 2; p++) {
                uint32_t addr = ds_cur_u + (uint32_t)((brow + p * 16) * 256
                              + (((k * 2 + bchunk_off) ^ bsw) << 4));
                uint32_t r0, r1, r2, r3;
                ldmatrix_x4(r0, r1, r2, r3, addr);
                bf[p * 2 + 0][0] = r0; bf[p * 2 + 0][1] = r1;
                bf[p * 2 + 1][0] = r2; bf[p * 2 + 1][1] = r3;
            }
            #pragma unroll
            for (int mt = 0; mt < 2; mt++)
                #pragma unroll
                for (int nt = 0; nt < 4; nt++)
                    mma_16816(acc[mt][nt][0], acc[mt][nt][1], acc[mt][nt][2], acc[mt][nt][3],
                              a[mt][0], a[mt][1], a[mt][2], a[mt][3],
                              bf[nt][0], bf[nt][1]);
        }

        // ---- refill this buffer with chunk c+2 ASAP (overlaps epilogue) ----
        if (c < NCHUNK - 2) {
            __syncthreads();   // all warps done with ldmatrix on this buffer
            const char* src_base = reinterpret_cast<const char*>(Dbf_b + (size_t)(c + 2) * TN * DIM);
            uint32_t dst_base = sb + SM_DS0 + (uint32_t)((c & 1) * 16384);
            #pragma unroll
            for (int j = 0; j < 4; j++) {
                int idx = tid + 256 * j;
                int r = idx >> 4, cc = idx & 15;
                cp_async16(dst_base + (uint32_t)(r * 256 + (((cc ^ (r & 7)) << 4))),
                           src_base + r * 256 + cc * 16);
            }
            cp_commit();
        }

        // ---- fused epilogue: neg_dist = (2q).d - d^2 ; running max ----
        #pragma unroll
        for (int nt = 0; nt < 4; nt++) {
            float2 ds2 = *reinterpret_cast<float2*>(&dsq_s[c * TN + wn * 32 + nt * 8 + tc * 2]);
            #pragma unroll
            for (int mt = 0; mt < 2; mt++) {
                rlo[mt] = fmaxf(rlo[mt], fmaxf(acc[mt][nt][0] - ds2.x, acc[mt][nt][1] - ds2.y));
                rhi[mt] = fmaxf(rhi[mt], fmaxf(acc[mt][nt][2] - ds2.x, acc[mt][nt][3] - ds2.y));
            }
        }
    }

    // ---- cross-lane max (cols in lane bits 0..1) ----
    #pragma unroll
    for (int mt = 0; mt < 2; mt++) {
        rlo[mt] = fmaxf(rlo[mt], __shfl_xor_sync(0xffffffffu, rlo[mt], 1));
        rlo[mt] = fmaxf(rlo[mt], __shfl_xor_sync(0xffffffffu, rlo[mt], 2));
        rhi[mt] = fmaxf(rhi[mt], __shfl_xor_sync(0xffffffffu, rhi[mt], 1));
        rhi[mt] = fmaxf(rhi[mt], __shfl_xor_sync(0xffffffffu, rhi[mt], 2));
    }
    if (tc == 0) {
        #pragma unroll
        for (int mt = 0; mt < 2; mt++) {
            maxbuf[(wm * 32 + mt * 16 + tg) * 2 + wn]     = rlo[mt];
            maxbuf[(wm * 32 + mt * 16 + 8 + tg) * 2 + wn] = rhi[mt];
        }
    }
    __syncthreads();

    // ---- row max across 2 warp-cols, subtract ||q||^2, block sum ----
    float val = 0.0f;
    if (tid < TM) {
        float2 m2 = *reinterpret_cast<float2*>(&maxbuf[tid * 2]);
        val = fmaxf(m2.x, m2.y) - qsq[tid];
    }
    #pragma unroll
    for (int o = 16; o > 0; o >>= 1) val += __shfl_xor_sync(0xffffffffu, val, o);
    if (l == 0) red[w] = val;
    __syncthreads();
    if (tid == 0) {
        float s = 0.0f;
        #pragma unroll
        for (int i = 0; i < 8; i++) s += red[i];
        atomicAdd(&out[b], s);
    }
}

extern "C" void kernel_launch(void* const* d_in, const int* in_sizes, int n_in,
                              void* d_out, int out_size) {
    const float* Qg = (const float*)d_in[0];
    const float* Dg = (const float*)d_in[1];
    float* out = (float*)d_out;

    static int attr_set = 0;
    if (!attr_set) {
        cudaFuncSetAttribute(colbert_mma_kernel,
                             cudaFuncAttributeMaxDynamicSharedMemorySize, SMEM_TOTAL);
        attr_set = 1;
    }

    convert_d_kernel<<<(B_ * LD_) / 128, NTHREADS>>>(Dg, out);
    colbert_mma_kernel<<<B_ * (LQ_ / TM), NTHREADS, SMEM_TOTAL>>>(Qg, out);
}

// round 9
// speedup vs baseline: 1.0250x; 1.0250x over previous
#include <cuda_runtime.h>
#include <cuda_bf16.h>
#include <cstdint>

#define B_    128
#define LQ_   512
#define LD_   512
#define DIM   128
#define TM    128            // q rows per CTA
#define TN    64             // doc rows per chunk
#define NCHUNK (LD_ / TN)    // 8
#define NTHREADS 256

// ---- global scratch: pre-converted bf16 D + exact fp32 row norms ----
__device__ __nv_bfloat16 g_Dbf[B_ * LD_ * DIM];   // 16 MB
__device__ float         g_Dsq[B_ * LD_];         // 256 KB

// ---- kernel-2 smem layout (bytes) ----
#define SM_QS    0                      // 128x128 bf16 swizzled = 32768
#define SM_DS0   32768                  // bf16 chunk buf 0 (16384)
#define SM_DS1   49152                  // bf16 chunk buf 1 (16384)
#define SM_DSQ   65536                  // 512 floats = 2048
#define SM_QSQ   67584                  // 128 floats = 512
#define SM_MAX   68096                  // 128*2 floats = 1024
#define SM_RED   69120                  // 8 floats
#define SMEM_TOTAL (SM_RED + 64)        // 69184

__device__ __forceinline__ uint32_t smem_u32(const void* p) {
    uint32_t a;
    asm("{ .reg .u64 t; cvta.to.shared.u64 t, %1; cvt.u32.u64 %0, t; }" : "=r"(a) : "l"(p));
    return a;
}

__device__ __forceinline__ void ldmatrix_x4(uint32_t& r0, uint32_t& r1,
                                            uint32_t& r2, uint32_t& r3, uint32_t addr) {
    asm volatile("ldmatrix.sync.aligned.m8n8.x4.shared.b16 {%0,%1,%2,%3}, [%4];"
                 : "=r"(r0), "=r"(r1), "=r"(r2), "=r"(r3) : "r"(addr));
}

__device__ __forceinline__ void mma_16816(float& c0, float& c1, float& c2, float& c3,
                                          uint32_t a0, uint32_t a1, uint32_t a2, uint32_t a3,
                                          uint32_t b0, uint32_t b1) {
    asm volatile("mma.sync.aligned.m16n8k16.row.col.f32.bf16.bf16.f32 "
                 "{%0,%1,%2,%3}, {%4,%5,%6,%7}, {%8,%9}, {%0,%1,%2,%3};"
                 : "+f"(c0), "+f"(c1), "+f"(c2), "+f"(c3)
                 : "r"(a0), "r"(a1), "r"(a2), "r"(a3), "r"(b0), "r"(b1));
}

__device__ __forceinline__ void cp_async16(uint32_t dst, const void* src) {
    asm volatile("cp.async.cg.shared.global [%0], [%1], 16;" :: "r"(dst), "l"(src));
}
__device__ __forceinline__ void cp_commit() {
    asm volatile("cp.async.commit_group;" ::: "memory");
}
template <int N>
__device__ __forceinline__ void cp_wait() {
    asm volatile("cp.async.wait_group %0;" :: "n"(N) : "memory");
}

// ================= kernel 1: D fp32 -> bf16 + exact row norms (+ zero out) ====
__global__ void __launch_bounds__(NTHREADS)
convert_d_kernel(const float* __restrict__ Dg, float* __restrict__ out) {
    const int tid = threadIdx.x;
    const int w = tid >> 5, l = tid & 31;
    const int rsub = l >> 3;
    const int piece = l & 7;

    if (blockIdx.x == 0 && tid < B_) out[tid] = 0.0f;

    #pragma unroll
    for (int pass = 0; pass < 4; pass++) {
        int row = blockIdx.x * 128 + w * 16 + pass * 4 + rsub;
        const float4* src = reinterpret_cast<const float4*>(Dg + (size_t)row * DIM);
        float4 v[4];
        #pragma unroll
        for (int i = 0; i < 4; i++) v[i] = src[piece + 8 * i];

        float s = 0.0f;
        #pragma unroll
        for (int i = 0; i < 4; i++)
            s += v[i].x * v[i].x + v[i].y * v[i].y + v[i].z * v[i].z + v[i].w * v[i].w;
        s += __shfl_xor_sync(0xffffffffu, s, 1);
        s += __shfl_xor_sync(0xffffffffu, s, 2);
        s += __shfl_xor_sync(0xffffffffu, s, 4);
        if (piece == 0) g_Dsq[row] = s;

        uint2* drow = reinterpret_cast<uint2*>(g_Dbf + (size_t)row * DIM);
        #pragma unroll
        for (int i = 0; i < 4; i++) {
            __nv_bfloat162 p0 = __floats2bfloat162_rn(v[i].x, v[i].y);
            __nv_bfloat162 p1 = __floats2bfloat162_rn(v[i].z, v[i].w);
            drow[piece + 8 * i] = make_uint2(*reinterpret_cast<uint32_t*>(&p0),
                                             *reinterpret_cast<uint32_t*>(&p1));
        }
    }
}

// ================= kernel 2: GEMM + fused max/sum epilogue =================
__global__ void __launch_bounds__(NTHREADS, 3)
colbert_mma_kernel(const float* __restrict__ Qg, float* __restrict__ out) {
    extern __shared__ char smem[];
    const uint32_t sb = smem_u32(smem);
    float* dsq_s  = reinterpret_cast<float*>(smem + SM_DSQ);
    float* qsq    = reinterpret_cast<float*>(smem + SM_QSQ);
    float* maxbuf = reinterpret_cast<float*>(smem + SM_MAX);
    float* red    = reinterpret_cast<float*>(smem + SM_RED);

    const int tid = threadIdx.x;
    const int w = tid >> 5, l = tid & 31;
    const int wm = w >> 1;               // 0..3 : 32-row M block
    const int wn = w & 1;                // 0..1 : 32-col N block

    const int b  = blockIdx.x >> 2;
    const int qt = blockIdx.x & 3;
    const float* Qb = Qg + ((size_t)(b * LQ_ + qt * TM)) * DIM;
    const __nv_bfloat16* Dbf_b = g_Dbf + (size_t)b * LD_ * DIM;

    // ---- issue cp.async for chunks 0 and 1 (bf16, swizzled dst) ----
    {
        #pragma unroll
        for (int cbuf = 0; cbuf < 2; cbuf++) {
            const char* src_base = reinterpret_cast<const char*>(Dbf_b + (size_t)cbuf * TN * DIM);
            uint32_t dst_base = sb + SM_DS0 + (uint32_t)(cbuf * 16384);
            #pragma unroll
            for (int j = 0; j < 4; j++) {
                int idx = tid + 256 * j;
                int r = idx >> 4, cc = idx & 15;
                cp_async16(dst_base + (uint32_t)(r * 256 + (((cc ^ (r & 7)) << 4))),
                           src_base + r * 256 + cc * 16);
            }
            cp_commit();
        }
    }

    // ---- convert Q tile fp32 -> bf16(2*q) swizzled smem + qsq (overlapped) ----
    {
        char* qs = smem + SM_QS;
        #pragma unroll
        for (int j = 0; j < TM / 8; j++) {
            int row = j * 8 + w;
            float4 v = reinterpret_cast<const float4*>(Qb)[row * 32 + l];
            float s = v.x * v.x + v.y * v.y + v.z * v.z + v.w * v.w;
            #pragma unroll
            for (int o = 16; o > 0; o >>= 1) s += __shfl_xor_sync(0xffffffffu, s, o);
            if (l == 0) qsq[row] = s;
            __nv_bfloat162 p0 = __floats2bfloat162_rn(2.0f * v.x, 2.0f * v.y);
            __nv_bfloat162 p1 = __floats2bfloat162_rn(2.0f * v.z, 2.0f * v.w);
            uint2 pk = make_uint2(*reinterpret_cast<uint32_t*>(&p0),
                                  *reinterpret_cast<uint32_t*>(&p1));
            uint32_t addr = (uint32_t)(row * 256 + (((l >> 1) ^ (row & 7)) << 4) + ((l & 1) << 3));
            *reinterpret_cast<uint2*>(qs + addr) = pk;
        }
    }
    // ---- whole-batch doc norms into smem (512 floats) ----
    {
        const float* src = g_Dsq + b * LD_;
        dsq_s[tid] = src[tid];
        dsq_s[tid + 256] = src[tid + 256];
    }

    // ---- ldmatrix lane addressing (validated structure) ----
    const int jj = l >> 3;
    const int rr = l & 7;
    const int arow = wm * 32 + ((jj & 1) << 3) + rr;
    const int achunk_off = jj >> 1;
    const int asw = arow & 7;
    const int brow = wn * 32 + ((jj >> 1) << 3) + rr;
    const int bchunk_off = jj & 1;
    const int bsw = brow & 7;

    const int tg = l >> 2;
    const int tc = l & 3;

    float rlo[2], rhi[2];
    #pragma unroll
    for (int mt = 0; mt < 2; mt++) { rlo[mt] = -3.402823e38f; rhi[mt] = -3.402823e38f; }

    #pragma unroll
    for (int c = 0; c < NCHUNK; c++) {
        if (c < NCHUNK - 1) cp_wait<1>(); else cp_wait<0>();
        __syncthreads();   // chunk c visible to all

        const uint32_t ds_cur_u = sb + SM_DS0 + (uint32_t)((c & 1) * 16384);

        float acc[2][4][4];
        #pragma unroll
        for (int mt = 0; mt < 2; mt++)
            #pragma unroll
            for (int nt = 0; nt < 4; nt++)
                #pragma unroll
                for (int e = 0; e < 4; e++) acc[mt][nt][e] = 0.0f;

        #pragma unroll
        for (int k = 0; k < 8; k++) {
            // per-warp k rotation: decorrelates LDSM/HMMA bursts across warps,
            // so L1 and tensor overlap instead of alternating (convoy breaker).
            const int kk = (k + w) & 7;
            uint32_t a[2][4];
            #pragma unroll
            for (int mt = 0; mt < 2; mt++) {
                uint32_t addr = sb + SM_QS + (uint32_t)((arow + mt * 16) * 256
                              + (((kk * 2 + achunk_off) ^ asw) << 4));
                ldmatrix_x4(a[mt][0], a[mt][1], a[mt][2], a[mt][3], addr);
            }
            uint32_t bf[4][2];
            #pragma unroll
            for (int p = 0; p < 2; p++) {
                uint32_t addr = ds_cur_u + (uint32_t)((brow + p * 16) * 256
                              + (((kk * 2 + bchunk_off) ^ bsw) << 4));
                uint32_t r0, r1, r2, r3;
                ldmatrix_x4(r0, r1, r2, r3, addr);
                bf[p * 2 + 0][0] = r0; bf[p * 2 + 0][1] = r1;
                bf[p * 2 + 1][0] = r2; bf[p * 2 + 1][1] = r3;
            }
            #pragma unroll
            for (int mt = 0; mt < 2; mt++)
                #pragma unroll
                for (int nt = 0; nt < 4; nt++)
                    mma_16816(acc[mt][nt][0], acc[mt][nt][1], acc[mt][nt][2], acc[mt][nt][3],
                              a[mt][0], a[mt][1], a[mt][2], a[mt][3],
                              bf[nt][0], bf[nt][1]);
        }

        // ---- refill this buffer with chunk c+2 ASAP (overlaps epilogue) ----
        if (c < NCHUNK - 2) {
            __syncthreads();   // all warps done with ldmatrix on this buffer
            const char* src_base = reinterpret_cast<const char*>(Dbf_b + (size_t)(c + 2) * TN * DIM);
            uint32_t dst_base = sb + SM_DS0 + (uint32_t)((c & 1) * 16384);
            #pragma unroll
            for (int j = 0; j < 4; j++) {
                int idx = tid + 256 * j;
                int r = idx >> 4, cc = idx & 15;
                cp_async16(dst_base + (uint32_t)(r * 256 + (((cc ^ (r & 7)) << 4))),
                           src_base + r * 256 + cc * 16);
            }
            cp_commit();
        }

        // ---- fused epilogue: neg_dist = (2q).d - d^2 ; running max ----
        #pragma unroll
        for (int nt = 0; nt < 4; nt++) {
            float2 ds2 = *reinterpret_cast<float2*>(&dsq_s[c * TN + wn * 32 + nt * 8 + tc * 2]);
            #pragma unroll
            for (int mt = 0; mt < 2; mt++) {
                rlo[mt] = fmaxf(rlo[mt], fmaxf(acc[mt][nt][0] - ds2.x, acc[mt][nt][1] - ds2.y));
                rhi[mt] = fmaxf(rhi[mt], fmaxf(acc[mt][nt][2] - ds2.x, acc[mt][nt][3] - ds2.y));
            }
        }
    }

    // ---- cross-lane max (cols in lane bits 0..1) ----
    #pragma unroll
    for (int mt = 0; mt < 2; mt++) {
        rlo[mt] = fmaxf(rlo[mt], __shfl_xor_sync(0xffffffffu, rlo[mt], 1));
        rlo[mt] = fmaxf(rlo[mt], __shfl_xor_sync(0xffffffffu, rlo[mt], 2));
        rhi[mt] = fmaxf(rhi[mt], __shfl_xor_sync(0xffffffffu, rhi[mt], 1));
        rhi[mt] = fmaxf(rhi[mt], __shfl_xor_sync(0xffffffffu, rhi[mt], 2));
    }
    if (tc == 0) {
        #pragma unroll
        for (int mt = 0; mt < 2; mt++) {
            maxbuf[(wm * 32 + mt * 16 + tg) * 2 + wn]     = rlo[mt];
            maxbuf[(wm * 32 + mt * 16 + 8 + tg) * 2 + wn] = rhi[mt];
        }
    }
    __syncthreads();

    // ---- row max across 2 warp-cols, subtract ||q||^2, block sum ----
    float val = 0.0f;
    if (tid < TM) {
        float2 m2 = *reinterpret_cast<float2*>(&maxbuf[tid * 2]);
        val = fmaxf(m2.x, m2.y) - qsq[tid];
    }
    #pragma unroll
    for (int o = 16; o > 0; o >>= 1) val += __shfl_xor_sync(0xffffffffu, val, o);
    if (l == 0) red[w] = val;
    __syncthreads();
    if (tid == 0) {
        float s = 0.0f;
        #pragma unroll
        for (int i = 0; i < 8; i++) s += red[i];
        atomicAdd(&out[b], s);
    }
}

extern "C" void kernel_launch(void* const* d_in, const int* in_sizes, int n_in,
                              void* d_out, int out_size) {
    const float* Qg = (const float*)d_in[0];
    const float* Dg = (const float*)d_in[1];
    float* out = (float*)d_out;

    static int attr_set = 0;
    if (!attr_set) {
        cudaFuncSetAttribute(colbert_mma_kernel,
                             cudaFuncAttributeMaxDynamicSharedMemorySize, SMEM_TOTAL);
        attr_set = 1;
    }

    convert_d_kernel<<<(B_ * LD_) / 128, NTHREADS>>>(Dg, out);
    colbert_mma_kernel<<<B_ * (LQ_ / TM), NTHREADS, SMEM_TOTAL>>>(Qg, out);
}

// round 10
// speedup vs baseline: 1.0444x; 1.0189x over previous
#include <cuda_runtime.h>
#include <cuda_fp16.h>
#include <cstdint>

#define B_    128
#define LQ_   512
#define LD_   512
#define DIM   128
#define TM    128            // q rows per CTA
#define TN    64             // doc rows per chunk
#define NCHUNK (LD_ / TN)    // 8
#define NTHREADS 256

// ---- global scratch: pre-converted fp16 D + exact fp32 row norms ----
__device__ __half g_Dh[B_ * LD_ * DIM];           // 16 MB
__device__ float  g_Dsq[B_ * LD_];                // 256 KB

// ---- kernel-2 smem layout (bytes) ----
#define SM_QS    0                      // 128x128 fp16 swizzled = 32768
#define SM_DS0   32768                  // fp16 chunk buf 0 (16384)
#define SM_DS1   49152                  // fp16 chunk buf 1 (16384)
#define SM_DSQ   65536                  // 512 floats = 2048
#define SM_QSQ   67584                  // 128 floats = 512
#define SM_MAX   68096                  // 128*2 floats = 1024
#define SM_RED   69120                  // 8 floats
#define SMEM_TOTAL (SM_RED + 64)        // 69184

__device__ __forceinline__ uint32_t smem_u32(const void* p) {
    uint32_t a;
    asm("{ .reg .u64 t; cvta.to.shared.u64 t, %1; cvt.u32.u64 %0, t; }" : "=r"(a) : "l"(p));
    return a;
}

__device__ __forceinline__ void ldmatrix_x4(uint32_t& r0, uint32_t& r1,
                                            uint32_t& r2, uint32_t& r3, uint32_t addr) {
    asm volatile("ldmatrix.sync.aligned.m8n8.x4.shared.b16 {%0,%1,%2,%3}, [%4];"
                 : "=r"(r0), "=r"(r1), "=r"(r2), "=r"(r3) : "r"(addr));
}

// f16 in / f16 acc: D,C = 2 regs (4 halves) -> half the accumulator operand traffic
__device__ __forceinline__ void mma_16816_f16(uint32_t& c0, uint32_t& c1,
                                              uint32_t a0, uint32_t a1, uint32_t a2, uint32_t a3,
                                              uint32_t b0, uint32_t b1) {
    asm volatile("mma.sync.aligned.m16n8k16.row.col.f16.f16.f16.f16 "
                 "{%0,%1}, {%2,%3,%4,%5}, {%6,%7}, {%0,%1};"
                 : "+r"(c0), "+r"(c1)
                 : "r"(a0), "r"(a1), "r"(a2), "r"(a3), "r"(b0), "r"(b1));
}

__device__ __forceinline__ void cp_async16(uint32_t dst, const void* src) {
    asm volatile("cp.async.cg.shared.global [%0], [%1], 16;" :: "r"(dst), "l"(src));
}
__device__ __forceinline__ void cp_commit() {
    asm volatile("cp.async.commit_group;" ::: "memory");
}
template <int N>
__device__ __forceinline__ void cp_wait() {
    asm volatile("cp.async.wait_group %0;" :: "n"(N) : "memory");
}

// ================= kernel 1: D fp32 -> fp16 + exact row norms (+ zero out) ====
__global__ void __launch_bounds__(NTHREADS)
convert_d_kernel(const float* __restrict__ Dg, float* __restrict__ out) {
    const int tid = threadIdx.x;
    const int w = tid >> 5, l = tid & 31;
    const int rsub = l >> 3;
    const int piece = l & 7;

    if (blockIdx.x == 0 && tid < B_) out[tid] = 0.0f;

    #pragma unroll
    for (int pass = 0; pass < 4; pass++) {
        int row = blockIdx.x * 128 + w * 16 + pass * 4 + rsub;
        const float4* src = reinterpret_cast<const float4*>(Dg + (size_t)row * DIM);
        float4 v[4];
        #pragma unroll
        for (int i = 0; i < 4; i++) v[i] = src[piece + 8 * i];

        float s = 0.0f;
        #pragma unroll
        for (int i = 0; i < 4; i++)
            s += v[i].x * v[i].x + v[i].y * v[i].y + v[i].z * v[i].z + v[i].w * v[i].w;
        s += __shfl_xor_sync(0xffffffffu, s, 1);
        s += __shfl_xor_sync(0xffffffffu, s, 2);
        s += __shfl_xor_sync(0xffffffffu, s, 4);
        if (piece == 0) g_Dsq[row] = s;

        uint2* drow = reinterpret_cast<uint2*>(g_Dh + (size_t)row * DIM);
        #pragma unroll
        for (int i = 0; i < 4; i++) {
            __half2 p0 = __floats2half2_rn(v[i].x, v[i].y);
            __half2 p1 = __floats2half2_rn(v[i].z, v[i].w);
            drow[piece + 8 * i] = make_uint2(*reinterpret_cast<uint32_t*>(&p0),
                                             *reinterpret_cast<uint32_t*>(&p1));
        }
    }
}

// ================= kernel 2: GEMM + fused max/sum epilogue =================
__global__ void __launch_bounds__(NTHREADS, 3)
colbert_mma_kernel(const float* __restrict__ Qg, float* __restrict__ out) {
    extern __shared__ char smem[];
    const uint32_t sb = smem_u32(smem);
    float* dsq_s  = reinterpret_cast<float*>(smem + SM_DSQ);
    float* qsq    = reinterpret_cast<float*>(smem + SM_QSQ);
    float* maxbuf = reinterpret_cast<float*>(smem + SM_MAX);
    float* red    = reinterpret_cast<float*>(smem + SM_RED);

    const int tid = threadIdx.x;
    const int w = tid >> 5, l = tid & 31;
    const int wm = w >> 1;               // 0..3 : 32-row M block
    const int wn = w & 1;                // 0..1 : 32-col N block

    const int b  = blockIdx.x >> 2;
    const int qt = blockIdx.x & 3;
    const float* Qb = Qg + ((size_t)(b * LQ_ + qt * TM)) * DIM;
    const __half* Dh_b = g_Dh + (size_t)b * LD_ * DIM;

    // ---- issue cp.async for chunks 0 and 1 (fp16, swizzled dst) ----
    {
        #pragma unroll
        for (int cbuf = 0; cbuf < 2; cbuf++) {
            const char* src_base = reinterpret_cast<const char*>(Dh_b + (size_t)cbuf * TN * DIM);
            uint32_t dst_base = sb + SM_DS0 + (uint32_t)(cbuf * 16384);
            #pragma unroll
            for (int j = 0; j < 4; j++) {
                int idx = tid + 256 * j;
                int r = idx >> 4, cc = idx & 15;
                cp_async16(dst_base + (uint32_t)(r * 256 + (((cc ^ (r & 7)) << 4))),
                           src_base + r * 256 + cc * 16);
            }
            cp_commit();
        }
    }

    // ---- convert Q tile fp32 -> fp16(2*q) swizzled smem + qsq (overlapped) ----
    {
        char* qs = smem + SM_QS;
        #pragma unroll
        for (int j = 0; j < TM / 8; j++) {
            int row = j * 8 + w;
            float4 v = reinterpret_cast<const float4*>(Qb)[row * 32 + l];
            float s = v.x * v.x + v.y * v.y + v.z * v.z + v.w * v.w;
            #pragma unroll
            for (int o = 16; o > 0; o >>= 1) s += __shfl_xor_sync(0xffffffffu, s, o);
            if (l == 0) qsq[row] = s;
            __half2 p0 = __floats2half2_rn(2.0f * v.x, 2.0f * v.y);
            __half2 p1 = __floats2half2_rn(2.0f * v.z, 2.0f * v.w);
            uint2 pk = make_uint2(*reinterpret_cast<uint32_t*>(&p0),
                                  *reinterpret_cast<uint32_t*>(&p1));
            uint32_t addr = (uint32_t)(row * 256 + (((l >> 1) ^ (row & 7)) << 4) + ((l & 1) << 3));
            *reinterpret_cast<uint2*>(qs + addr) = pk;
        }
    }
    // ---- whole-batch doc norms into smem (512 floats) ----
    {
        const float* src = g_Dsq + b * LD_;
        dsq_s[tid] = src[tid];
        dsq_s[tid + 256] = src[tid + 256];
    }

    // ---- ldmatrix lane addressing (validated structure) ----
    const int jj = l >> 3;
    const int rr = l & 7;
    const int arow = wm * 32 + ((jj & 1) << 3) + rr;
    const int achunk_off = jj >> 1;
    const int asw = arow & 7;
    const int brow = wn * 32 + ((jj >> 1) << 3) + rr;
    const int bchunk_off = jj & 1;
    const int bsw = brow & 7;

    const int tg = l >> 2;
    const int tc = l & 3;

    float rlo[2], rhi[2];
    #pragma unroll
    for (int mt = 0; mt < 2; mt++) { rlo[mt] = -3.402823e38f; rhi[mt] = -3.402823e38f; }

    #pragma unroll
    for (int c = 0; c < NCHUNK; c++) {
        if (c < NCHUNK - 1) cp_wait<1>(); else cp_wait<0>();
        __syncthreads();   // chunk c visible to all

        const uint32_t ds_cur_u = sb + SM_DS0 + (uint32_t)((c & 1) * 16384);

        // f16 accumulators: 2 regs per mma tile (4 halves)
        uint32_t acc[2][4][2];
        #pragma unroll
        for (int mt = 0; mt < 2; mt++)
            #pragma unroll
            for (int nt = 0; nt < 4; nt++) { acc[mt][nt][0] = 0u; acc[mt][nt][1] = 0u; }

        #pragma unroll
        for (int k = 0; k < 8; k++) {
            const int kk = (k + w) & 7;   // per-warp k rotation (kept from R9)
            uint32_t a[2][4];
            #pragma unroll
            for (int mt = 0; mt < 2; mt++) {
                uint32_t addr = sb + SM_QS + (uint32_t)((arow + mt * 16) * 256
                              + (((kk * 2 + achunk_off) ^ asw) << 4));
                ldmatrix_x4(a[mt][0], a[mt][1], a[mt][2], a[mt][3], addr);
            }
            uint32_t bf[4][2];
            #pragma unroll
            for (int p = 0; p < 2; p++) {
                uint32_t addr = ds_cur_u + (uint32_t)((brow + p * 16) * 256
                              + (((kk * 2 + bchunk_off) ^ bsw) << 4));
                uint32_t r0, r1, r2, r3;
                ldmatrix_x4(r0, r1, r2, r3, addr);
                bf[p * 2 + 0][0] = r0; bf[p * 2 + 0][1] = r1;
                bf[p * 2 + 1][0] = r2; bf[p * 2 + 1][1] = r3;
            }
            #pragma unroll
            for (int mt = 0; mt < 2; mt++)
                #pragma unroll
                for (int nt = 0; nt < 4; nt++)
                    mma_16816_f16(acc[mt][nt][0], acc[mt][nt][1],
                                  a[mt][0], a[mt][1], a[mt][2], a[mt][3],
                                  bf[nt][0], bf[nt][1]);
        }

        // ---- refill this buffer with chunk c+2 ASAP (overlaps epilogue) ----
        if (c < NCHUNK - 2) {
            __syncthreads();   // all warps done with ldmatrix on this buffer
            const char* src_base = reinterpret_cast<const char*>(Dh_b + (size_t)(c + 2) * TN * DIM);
            uint32_t dst_base = sb + SM_DS0 + (uint32_t)((c & 1) * 16384);
            #pragma unroll
            for (int j = 0; j < 4; j++) {
                int idx = tid + 256 * j;
                int r = idx >> 4, cc = idx & 15;
                cp_async16(dst_base + (uint32_t)(r * 256 + (((cc ^ (r & 7)) << 4))),
                           src_base + r * 256 + cc * 16);
            }
            cp_commit();
        }

        // ---- fused epilogue: neg_dist = (2q).d - d^2 ; running max ----
        // acc reg0 = (row tg,   cols tc*2, tc*2+1), reg1 = (row tg+8, same cols)
        #pragma unroll
        for (int nt = 0; nt < 4; nt++) {
            float2 ds2 = *reinterpret_cast<float2*>(&dsq_s[c * TN + wn * 32 + nt * 8 + tc * 2]);
            #pragma unroll
            for (int mt = 0; mt < 2; mt++) {
                float2 lo = __half22float2(*reinterpret_cast<__half2*>(&acc[mt][nt][0]));
                float2 hi = __half22float2(*reinterpret_cast<__half2*>(&acc[mt][nt][1]));
                rlo[mt] = fmaxf(rlo[mt], fmaxf(lo.x - ds2.x, lo.y - ds2.y));
                rhi[mt] = fmaxf(rhi[mt], fmaxf(hi.x - ds2.x, hi.y - ds2.y));
            }
        }
    }

    // ---- cross-lane max (cols in lane bits 0..1) ----
    #pragma unroll
    for (int mt = 0; mt < 2; mt++) {
        rlo[mt] = fmaxf(rlo[mt], __shfl_xor_sync(0xffffffffu, rlo[mt], 1));
        rlo[mt] = fmaxf(rlo[mt], __shfl_xor_sync(0xffffffffu, rlo[mt], 2));
        rhi[mt] = fmaxf(rhi[mt], __shfl_xor_sync(0xffffffffu, rhi[mt], 1));
        rhi[mt] = fmaxf(rhi[mt], __shfl_xor_sync(0xffffffffu, rhi[mt], 2));
    }
    if (tc == 0) {
        #pragma unroll
        for (int mt = 0; mt < 2; mt++) {
            maxbuf[(wm * 32 + mt * 16 + tg) * 2 + wn]     = rlo[mt];
            maxbuf[(wm * 32 + mt * 16 + 8 + tg) * 2 + wn] = rhi[mt];
        }
    }
    __syncthreads();

    // ---- row max across 2 warp-cols, subtract ||q||^2, block sum ----
    float val = 0.0f;
    if (tid < TM) {
        float2 m2 = *reinterpret_cast<float2*>(&maxbuf[tid * 2]);
        val = fmaxf(m2.x, m2.y) - qsq[tid];
    }
    #pragma unroll
    for (int o = 16; o > 0; o >>= 1) val += __shfl_xor_sync(0xffffffffu, val, o);
    if (l == 0) red[w] = val;
    __syncthreads();
    if (tid == 0) {
        float s = 0.0f;
        #pragma unroll
        for (int i = 0; i < 8; i++) s += red[i];
        atomicAdd(&out[b], s);
    }
}

extern "C" void kernel_launch(void* const* d_in, const int* in_sizes, int n_in,
                              void* d_out, int out_size) {
    const float* Qg = (const float*)d_in[0];
    const float* Dg = (const float*)d_in[1];
    float* out = (float*)d_out;

    static int attr_set = 0;
    if (!attr_set) {
        cudaFuncSetAttribute(colbert_mma_kernel,
                             cudaFuncAttributeMaxDynamicSharedMemorySize, SMEM_TOTAL);
        attr_set = 1;
    }

    convert_d_kernel<<<(B_ * LD_) / 128, NTHREADS>>>(Dg, out);
    colbert_mma_kernel<<<B_ * (LQ_ / TM), NTHREADS, SMEM_TOTAL>>>(Qg, out);
}